// round 4
// baseline (speedup 1.0000x reference)
#include <cuda_runtime.h>
#include <math.h>

#define CHANNELS 192
#define CPARAMS  43

// Table: v range [-6.5, 6.5], step h = 1/128 (0.5 = 64 steps, 1.0 = 128 steps)
#define NK      1664             // 13 * 128 intervals per channel
#define OFFK    128              // 1.0 / h
#define NC      (NK + OFFK + 3)  // 1795 CDF samples per channel
#define H_STEP  (1.0f / 128.0f)
#define INV_H   128.0f
#define V_OFF   832.0f           // 6.5 * 128

#define GRP      8               // channels per main-kernel block
#define NGRP     (CHANNELS / GRP)    // 24
#define ROWSPLIT 16
#define MAIN_THREADS 512
#define SMEM_BYTES (NK * GRP * 16)   // 212,992 B

// CDF samples (~1.4 MB)
__device__ float g_csamp[CHANNELS * NC];
// Cubic coefficients, stored transposed per group: [group][interval][ch_in_group]
// entry = g_coef[(g*NK + i)*GRP + c], ~5.1 MB (L2-resident)
__device__ float4 g_coef[NGRP * NK * GRP];

// ---------------------------------------------------------------------------

__device__ __forceinline__ float softplus_acc(float v) {
    return fmaxf(v, 0.0f) + log1pf(expf(-fabsf(v)));
}
__device__ __forceinline__ float tanh_fast(float x) {
    x = fminf(fmaxf(x, -20.0f), 20.0f);
    float e = __expf(-2.0f * x);
    return __fdividef(1.0f - e, 1.0f + e);
}
__device__ __forceinline__ float sigmoid_fast(float x) {
    return __fdividef(1.0f, 1.0f + __expf(-x));
}

// Exact CDF eval from a 43-float constant block
__device__ __forceinline__ float cdf_eval(float u, const float* __restrict__ K) {
    float h[3];
#pragma unroll
    for (int j = 0; j < 3; j++) {
        h[j] = fmaf(u, K[j], K[3 + j]);
        h[j] = fmaf(K[6 + j], tanh_fast(h[j]), h[j]);
    }
    float y[3];
#pragma unroll
    for (int p = 0; p < 3; p++) y[p] = K[18 + p];
#pragma unroll
    for (int i = 0; i < 3; i++)
#pragma unroll
        for (int p = 0; p < 3; p++) y[p] = fmaf(h[i], K[9 + i * 3 + p], y[p]);
#pragma unroll
    for (int j = 0; j < 3; j++) y[j] = fmaf(K[21 + j], tanh_fast(y[j]), y[j]);
    float z[3];
#pragma unroll
    for (int p = 0; p < 3; p++) z[p] = K[33 + p];
#pragma unroll
    for (int i = 0; i < 3; i++)
#pragma unroll
        for (int p = 0; p < 3; p++) z[p] = fmaf(y[i], K[24 + i * 3 + p], z[p]);
#pragma unroll
    for (int j = 0; j < 3; j++) z[j] = fmaf(K[36 + j], tanh_fast(z[j]), z[j]);
    float f = K[42];
#pragma unroll
    for (int i = 0; i < 3; i++) f = fmaf(z[i], K[39 + i], f);
    return sigmoid_fast(f);
}

// Sample CDF on grid. grid = (CHANNELS, JCHUNKS), 256 threads.
#define JCHUNKS 2
__global__ void __launch_bounds__(256)
de_sample(const float* __restrict__ a0, const float* __restrict__ a1,
          const float* __restrict__ a2,
          const float* __restrict__ b0, const float* __restrict__ b1,
          const float* __restrict__ b2, const float* __restrict__ b3,
          const float* __restrict__ H0, const float* __restrict__ H1,
          const float* __restrict__ H2, const float* __restrict__ H3) {
    __shared__ float sk[CPARAMS];
    const int c = blockIdx.x;
    const int t = threadIdx.x;
    if (t < CPARAMS) {
        float v;
        if      (t < 3)  v = softplus_acc(H0[c * 3 + t]);
        else if (t < 6)  v = b0[c * 3 + (t - 3)];
        else if (t < 9)  v = tanhf(a0[c * 3 + (t - 6)]);
        else if (t < 18) v = softplus_acc(H1[c * 9 + (t - 9)]);
        else if (t < 21) v = b1[c * 3 + (t - 18)];
        else if (t < 24) v = tanhf(a1[c * 3 + (t - 21)]);
        else if (t < 33) v = softplus_acc(H2[c * 9 + (t - 24)]);
        else if (t < 36) v = b2[c * 3 + (t - 33)];
        else if (t < 39) v = tanhf(a2[c * 3 + (t - 36)]);
        else if (t < 42) v = softplus_acc(H3[c * 3 + (t - 39)]);
        else             v = b3[c];
        sk[t] = v;
    }
    __syncthreads();
    const float u0 = -7.0f - H_STEP;   // (LO - 0.5) - h
    for (int j = blockIdx.y * 256 + t; j < NC; j += JCHUNKS * 256) {
        float u = fmaf((float)j, H_STEP, u0);
        g_csamp[c * NC + j] = cdf_eval(u, sk);
    }
}

// Build Catmull-Rom coefficients; write into transposed-per-group layout.
__global__ void __launch_bounds__(256)
de_coef() {
    int idx = blockIdx.x * blockDim.x + threadIdx.x;
    if (idx >= CHANNELS * NK) return;
    int ch = idx / NK;
    int i  = idx - ch * NK;
    const float* cs = g_csamp + ch * NC;
    float s0 = cs[i + 0 + OFFK] - cs[i + 0];
    float s1 = cs[i + 1 + OFFK] - cs[i + 1];
    float s2 = cs[i + 2 + OFFK] - cs[i + 2];
    float s3 = cs[i + 3 + OFFK] - cs[i + 3];
    float A = s1;
    float B = 0.5f * (s2 - s0);
    float C = s0 - 2.5f * s1 + 2.0f * s2 - 0.5f * s3;
    float D = 0.5f * (s3 - s0) + 1.5f * (s1 - s2);
    int g = ch >> 3, c = ch & 7;
    g_coef[(g * NK + i) * GRP + c] = make_float4(A, B, C, D);
}

// Main kernel: SMEM-resident per-group table, conflict-free LDS.128 gather.
// grid = (NGRP, ROWSPLIT), 512 threads. SMEM layout s_tab[i*GRP + c].
#define UB 8
__global__ void __launch_bounds__(MAIN_THREADS)
de_main(const float* __restrict__ xin, float* __restrict__ out, int rows) {
    extern __shared__ float4 s_tab[];      // [NK][GRP]
    const int t = threadIdx.x;
    const int g = blockIdx.x;

    // Linear fill: global layout already matches SMEM layout.
    const float4* __restrict__ gsrc = g_coef + g * NK * GRP;
    for (int j = t; j < NK * GRP; j += MAIN_THREADS) s_tab[j] = gsrc[j];
    __syncthreads();

    const int c = t & (GRP - 1);           // channel within group
    const int rows_per_blk = rows / ROWSPLIT;            // 4096
    const int rpi = MAIN_THREADS / GRP;                  // 64 rows per iteration
    const int iters = rows_per_blk / rpi;                // 64
    const int r0 = blockIdx.y * rows_per_blk + (t >> 3);
    const int stride = rpi * CHANNELS;                   // elements per iteration
    int idx0 = r0 * CHANNELS + g * GRP + c;

#pragma unroll
    for (int ob = 0; ob < iters / UB; ob++) {
        float v[UB];
#pragma unroll
        for (int u = 0; u < UB; u++)
            v[u] = xin[idx0 + (ob * UB + u) * stride];

        float4 Cf[UB];
        float  tf[UB];
#pragma unroll
        for (int u = 0; u < UB; u++) {
            float uu = fmaf(v[u], INV_H, V_OFF);
            uu = fminf(fmaxf(uu, 0.0f), (float)NK - 0.001f);
            int i = (int)uu;
            tf[u] = uu - (float)i;
            Cf[u] = s_tab[i * GRP + c];
        }
#pragma unroll
        for (int u = 0; u < UB; u++) {
            out[idx0 + (ob * UB + u) * stride] =
                fmaf(tf[u], fmaf(tf[u], fmaf(tf[u], Cf[u].w, Cf[u].z), Cf[u].y), Cf[u].x);
        }
    }
}

// ---------------------------------------------------------------------------

extern "C" void kernel_launch(void* const* d_in, const int* in_sizes, int n_in,
                              void* d_out, int out_size) {
    const float* x  = (const float*)d_in[0];
    const float* a0 = (const float*)d_in[1];
    const float* a1 = (const float*)d_in[2];
    const float* a2 = (const float*)d_in[3];
    const float* b0 = (const float*)d_in[4];
    const float* b1 = (const float*)d_in[5];
    const float* b2 = (const float*)d_in[6];
    const float* b3 = (const float*)d_in[7];
    const float* H0 = (const float*)d_in[8];
    const float* H1 = (const float*)d_in[9];
    const float* H2 = (const float*)d_in[10];
    const float* H3 = (const float*)d_in[11];
    float* out = (float*)d_out;

    int total = in_sizes[0];
    int rows  = total / CHANNELS;    // 65536

    static int smem_set = 0;
    if (!smem_set) {
        cudaFuncSetAttribute(de_main, cudaFuncAttributeMaxDynamicSharedMemorySize,
                             SMEM_BYTES);
        smem_set = 1;
    }

    dim3 sgrid(CHANNELS, JCHUNKS);
    de_sample<<<sgrid, 256>>>(a0, a1, a2, b0, b1, b2, b3, H0, H1, H2, H3);
    de_coef<<<(CHANNELS * NK + 255) / 256, 256>>>();
    dim3 mgrid(NGRP, ROWSPLIT);
    de_main<<<mgrid, MAIN_THREADS, SMEM_BYTES>>>(x, out, rows);
}

// round 5
// speedup vs baseline: 1.1968x; 1.1968x over previous
#include <cuda_runtime.h>
#include <math.h>

#define CHANNELS 192
#define CPARAMS  43

// Table: v range [-6.5, 6.5], step h = 1/128
#define NK      1664             // 13 * 128 intervals per channel
#define OFFK    128              // 1.0 / h
#define NC      (NK + OFFK + 3)  // 1795 CDF samples per channel
#define H_STEP  (1.0f / 128.0f)
#define INV_H   128.0f
#define V_OFF   832.0f           // 6.5 * 128

#define GRP      8                       // channels per main-kernel block
#define NGRP     (CHANNELS / GRP)        // 24
#define NCHUNK   6                       // row chunks -> 24*6 = 144 blocks = 1 wave
#define MAIN_THREADS 1024
#define ROWS_PER_ITER (MAIN_THREADS / GRP)   // 128
#define UB 8
#define SMEM_BYTES (NK * GRP * 16)       // 212,992 B

// CDF samples (~1.4 MB)
__device__ float g_csamp[CHANNELS * NC];
// Cubic coefficients, transposed per group: g_coef[(g*NK + i)*GRP + c] (~5.1 MB)
__device__ float4 g_coef[NGRP * NK * GRP];

// ---------------------------------------------------------------------------

__device__ __forceinline__ float softplus_acc(float v) {
    return fmaxf(v, 0.0f) + log1pf(expf(-fabsf(v)));
}
__device__ __forceinline__ float tanh_fast(float x) {
    x = fminf(fmaxf(x, -20.0f), 20.0f);
    float e = __expf(-2.0f * x);
    return __fdividef(1.0f - e, 1.0f + e);
}
__device__ __forceinline__ float sigmoid_fast(float x) {
    return __fdividef(1.0f, 1.0f + __expf(-x));
}

__device__ __forceinline__ float cdf_eval(float u, const float* __restrict__ K) {
    float h[3];
#pragma unroll
    for (int j = 0; j < 3; j++) {
        h[j] = fmaf(u, K[j], K[3 + j]);
        h[j] = fmaf(K[6 + j], tanh_fast(h[j]), h[j]);
    }
    float y[3];
#pragma unroll
    for (int p = 0; p < 3; p++) y[p] = K[18 + p];
#pragma unroll
    for (int i = 0; i < 3; i++)
#pragma unroll
        for (int p = 0; p < 3; p++) y[p] = fmaf(h[i], K[9 + i * 3 + p], y[p]);
#pragma unroll
    for (int j = 0; j < 3; j++) y[j] = fmaf(K[21 + j], tanh_fast(y[j]), y[j]);
    float z[3];
#pragma unroll
    for (int p = 0; p < 3; p++) z[p] = K[33 + p];
#pragma unroll
    for (int i = 0; i < 3; i++)
#pragma unroll
        for (int p = 0; p < 3; p++) z[p] = fmaf(y[i], K[24 + i * 3 + p], z[p]);
#pragma unroll
    for (int j = 0; j < 3; j++) z[j] = fmaf(K[36 + j], tanh_fast(z[j]), z[j]);
    float f = K[42];
#pragma unroll
    for (int i = 0; i < 3; i++) f = fmaf(z[i], K[39 + i], f);
    return sigmoid_fast(f);
}

// Sample CDF: one eval per thread. grid = (CHANNELS, 8), 256 threads.
__global__ void __launch_bounds__(256)
de_sample(const float* __restrict__ a0, const float* __restrict__ a1,
          const float* __restrict__ a2,
          const float* __restrict__ b0, const float* __restrict__ b1,
          const float* __restrict__ b2, const float* __restrict__ b3,
          const float* __restrict__ H0, const float* __restrict__ H1,
          const float* __restrict__ H2, const float* __restrict__ H3) {
    __shared__ float sk[CPARAMS];
    const int c = blockIdx.x;
    const int t = threadIdx.x;
    if (t < CPARAMS) {
        float v;
        if      (t < 3)  v = softplus_acc(H0[c * 3 + t]);
        else if (t < 6)  v = b0[c * 3 + (t - 3)];
        else if (t < 9)  v = tanhf(a0[c * 3 + (t - 6)]);
        else if (t < 18) v = softplus_acc(H1[c * 9 + (t - 9)]);
        else if (t < 21) v = b1[c * 3 + (t - 18)];
        else if (t < 24) v = tanhf(a1[c * 3 + (t - 21)]);
        else if (t < 33) v = softplus_acc(H2[c * 9 + (t - 24)]);
        else if (t < 36) v = b2[c * 3 + (t - 33)];
        else if (t < 39) v = tanhf(a2[c * 3 + (t - 36)]);
        else if (t < 42) v = softplus_acc(H3[c * 3 + (t - 39)]);
        else             v = b3[c];
        sk[t] = v;
    }
    __syncthreads();
    int j = blockIdx.y * 256 + t;
    if (j < NC) {
        const float u0 = -7.0f - H_STEP;   // (LO - 0.5) - h
        float u = fmaf((float)j, H_STEP, u0);
        g_csamp[c * NC + j] = cdf_eval(u, sk);
    }
}

// Build Catmull-Rom coefficients into transposed-per-group layout.
__global__ void __launch_bounds__(256)
de_coef() {
    int idx = blockIdx.x * blockDim.x + threadIdx.x;
    if (idx >= CHANNELS * NK) return;
    int ch = idx / NK;
    int i  = idx - ch * NK;
    const float* cs = g_csamp + ch * NC;
    float s0 = cs[i + 0 + OFFK] - cs[i + 0];
    float s1 = cs[i + 1 + OFFK] - cs[i + 1];
    float s2 = cs[i + 2 + OFFK] - cs[i + 2];
    float s3 = cs[i + 3 + OFFK] - cs[i + 3];
    float A = s1;
    float B = 0.5f * (s2 - s0);
    float C = s0 - 2.5f * s1 + 2.0f * s2 - 0.5f * s3;
    float D = 0.5f * (s3 - s0) + 1.5f * (s1 - s2);
    int g = ch >> 3, c = ch & 7;
    g_coef[(g * NK + i) * GRP + c] = make_float4(A, B, C, D);
}

// Main: SMEM table, conflict-free LDS.128 gather, 32 warps/SM, single wave.
// grid = (NCHUNK, NGRP), 1024 threads.
__global__ void __launch_bounds__(MAIN_THREADS)
de_main(const float* __restrict__ xin, float* __restrict__ out, int rows) {
    extern __shared__ float4 s_tab[];      // [NK][GRP]
    const int t = threadIdx.x;
    const int g = blockIdx.y;

    const float4* __restrict__ gsrc = g_coef + g * NK * GRP;
#pragma unroll
    for (int j = 0; j < (NK * GRP) / MAIN_THREADS; j++)
        s_tab[j * MAIN_THREADS + t] = gsrc[j * MAIN_THREADS + t];
    __syncthreads();

    const int c   = t & (GRP - 1);
    const int rl  = t >> 3;                // 0..127
    const int col = g * GRP + c;

    // chunk rows: first 4 chunks get one extra row
    const int chunk = blockIdx.x;
    const int rbase = rows / NCHUNK;                       // 10922
    const int rextra = rows - rbase * NCHUNK;              // 4
    const int r0    = chunk * rbase + min(chunk, rextra);
    const int nrows = rbase + (chunk < rextra ? 1 : 0);
    const int r_end = r0 + nrows;

    int r = r0 + rl;
    const int nfull = nrows / (ROWS_PER_ITER * UB);

    for (int b = 0; b < nfull; b++) {
        float v[UB];
#pragma unroll
        for (int u = 0; u < UB; u++)
            v[u] = xin[(r + u * ROWS_PER_ITER) * CHANNELS + col];
#pragma unroll
        for (int u = 0; u < UB; u++) {
            float uu = fmaf(v[u], INV_H, V_OFF);
            uu = fminf(fmaxf(uu, 0.0f), (float)NK - 0.001f);
            int i = (int)uu;
            float tf = uu - (float)i;
            float4 C = s_tab[i * GRP + c];
            out[(r + u * ROWS_PER_ITER) * CHANNELS + col] =
                fmaf(tf, fmaf(tf, fmaf(tf, C.w, C.z), C.y), C.x);
        }
        r += ROWS_PER_ITER * UB;
    }
    // remainder rows
    for (; r < r_end; r += ROWS_PER_ITER) {
        float v = xin[r * CHANNELS + col];
        float uu = fmaf(v, INV_H, V_OFF);
        uu = fminf(fmaxf(uu, 0.0f), (float)NK - 0.001f);
        int i = (int)uu;
        float tf = uu - (float)i;
        float4 C = s_tab[i * GRP + c];
        out[r * CHANNELS + col] =
            fmaf(tf, fmaf(tf, fmaf(tf, C.w, C.z), C.y), C.x);
    }
}

// ---------------------------------------------------------------------------

extern "C" void kernel_launch(void* const* d_in, const int* in_sizes, int n_in,
                              void* d_out, int out_size) {
    const float* x  = (const float*)d_in[0];
    const float* a0 = (const float*)d_in[1];
    const float* a1 = (const float*)d_in[2];
    const float* a2 = (const float*)d_in[3];
    const float* b0 = (const float*)d_in[4];
    const float* b1 = (const float*)d_in[5];
    const float* b2 = (const float*)d_in[6];
    const float* b3 = (const float*)d_in[7];
    const float* H0 = (const float*)d_in[8];
    const float* H1 = (const float*)d_in[9];
    const float* H2 = (const float*)d_in[10];
    const float* H3 = (const float*)d_in[11];
    float* out = (float*)d_out;

    int total = in_sizes[0];
    int rows  = total / CHANNELS;    // 65536

    static int smem_set = 0;
    if (!smem_set) {
        cudaFuncSetAttribute(de_main, cudaFuncAttributeMaxDynamicSharedMemorySize,
                             SMEM_BYTES);
        smem_set = 1;
    }

    dim3 sgrid(CHANNELS, (NC + 255) / 256);
    de_sample<<<sgrid, 256>>>(a0, a1, a2, b0, b1, b2, b3, H0, H1, H2, H3);
    de_coef<<<(CHANNELS * NK + 255) / 256, 256>>>();
    dim3 mgrid(NCHUNK, NGRP);
    de_main<<<mgrid, MAIN_THREADS, SMEM_BYTES>>>(x, out, rows);
}

// round 6
// speedup vs baseline: 1.2412x; 1.0372x over previous
#include <cuda_runtime.h>
#include <math.h>

#define CHANNELS 192
#define CPARAMS  43

// Table: v range [-6.5, 6.5], step h = 1/128
#define NK      1664             // 13 * 128 intervals per channel
#define OFFK    128              // 1.0 / h
#define H_STEP  (1.0f / 128.0f)
#define INV_H   128.0f
#define V_OFF   832.0f           // 6.5 * 128

#define GRP      8                       // channels per main-kernel block
#define NGRP     (CHANNELS / GRP)        // 24
#define NCHUNK   6                       // 24*6 = 144 blocks = 1 wave
#define MAIN_THREADS 1024
#define ROWS_PER_ITER (MAIN_THREADS / GRP)   // 128
#define UB 16
#define SMEM_BYTES (NK * GRP * 16)       // 212,992 B

// prep kernel geometry
#define PREP_HALF    (NK / 2)            // 832 intervals per block
#define PREP_W       (PREP_HALF + 3)     // 835 CDF samples per window
#define PREP_THREADS 512

// Cubic coefficients, transposed per group: g_coef[(g*NK + i)*GRP + c] (~5.1 MB)
__device__ float4 g_coef[NGRP * NK * GRP];

// ---------------------------------------------------------------------------

__device__ __forceinline__ float softplus_acc(float v) {
    return fmaxf(v, 0.0f) + log1pf(expf(-fabsf(v)));
}
__device__ __forceinline__ float tanh_fast(float x) {
    x = fminf(fmaxf(x, -20.0f), 20.0f);
    float e = __expf(-2.0f * x);
    return __fdividef(1.0f - e, 1.0f + e);
}
__device__ __forceinline__ float sigmoid_fast(float x) {
    return __fdividef(1.0f, 1.0f + __expf(-x));
}

__device__ __forceinline__ float cdf_eval(float u, const float* __restrict__ K) {
    float h[3];
#pragma unroll
    for (int j = 0; j < 3; j++) {
        h[j] = fmaf(u, K[j], K[3 + j]);
        h[j] = fmaf(K[6 + j], tanh_fast(h[j]), h[j]);
    }
    float y[3];
#pragma unroll
    for (int p = 0; p < 3; p++) y[p] = K[18 + p];
#pragma unroll
    for (int i = 0; i < 3; i++)
#pragma unroll
        for (int p = 0; p < 3; p++) y[p] = fmaf(h[i], K[9 + i * 3 + p], y[p]);
#pragma unroll
    for (int j = 0; j < 3; j++) y[j] = fmaf(K[21 + j], tanh_fast(y[j]), y[j]);
    float z[3];
#pragma unroll
    for (int p = 0; p < 3; p++) z[p] = K[33 + p];
#pragma unroll
    for (int i = 0; i < 3; i++)
#pragma unroll
        for (int p = 0; p < 3; p++) z[p] = fmaf(y[i], K[24 + i * 3 + p], z[p]);
#pragma unroll
    for (int j = 0; j < 3; j++) z[j] = fmaf(K[36 + j], tanh_fast(z[j]), z[j]);
    float f = K[42];
#pragma unroll
    for (int i = 0; i < 3; i++) f = fmaf(z[i], K[39 + i], f);
    return sigmoid_fast(f);
}

// Fused prep: sample both CDF windows into SMEM, emit Catmull-Rom coefs.
// grid = (CHANNELS, 2), 512 threads. Block (c, half) covers intervals
// [half*832, half*832+832).
__global__ void __launch_bounds__(PREP_THREADS)
de_prep(const float* __restrict__ a0, const float* __restrict__ a1,
        const float* __restrict__ a2,
        const float* __restrict__ b0, const float* __restrict__ b1,
        const float* __restrict__ b2, const float* __restrict__ b3,
        const float* __restrict__ H0, const float* __restrict__ H1,
        const float* __restrict__ H2, const float* __restrict__ H3) {
    __shared__ float sk[CPARAMS];
    __shared__ float W1[PREP_W];   // cs[i0 + l]
    __shared__ float W2[PREP_W];   // cs[i0 + OFFK + l]
    const int c = blockIdx.x;
    const int t = threadIdx.x;
    const int i0 = blockIdx.y * PREP_HALF;

    if (t < CPARAMS) {
        float v;
        if      (t < 3)  v = softplus_acc(H0[c * 3 + t]);
        else if (t < 6)  v = b0[c * 3 + (t - 3)];
        else if (t < 9)  v = tanhf(a0[c * 3 + (t - 6)]);
        else if (t < 18) v = softplus_acc(H1[c * 9 + (t - 9)]);
        else if (t < 21) v = b1[c * 3 + (t - 18)];
        else if (t < 24) v = tanhf(a1[c * 3 + (t - 21)]);
        else if (t < 33) v = softplus_acc(H2[c * 9 + (t - 24)]);
        else if (t < 36) v = b2[c * 3 + (t - 33)];
        else if (t < 39) v = tanhf(a2[c * 3 + (t - 36)]);
        else if (t < 42) v = softplus_acc(H3[c * 3 + (t - 39)]);
        else             v = b3[c];
        sk[t] = v;
    }
    __syncthreads();

    const float u0 = -7.0f - H_STEP;   // cs[j] = cdf(u0 + j*h)
    for (int l = t; l < 2 * PREP_W; l += PREP_THREADS) {
        int  lw = (l < PREP_W) ? l : (l - PREP_W);
        int  j  = i0 + lw + ((l < PREP_W) ? 0 : OFFK);
        float u = fmaf((float)j, H_STEP, u0);
        float val = cdf_eval(u, sk);
        if (l < PREP_W) W1[lw] = val; else W2[lw] = val;
    }
    __syncthreads();

    const int g  = c >> 3;
    const int cg = c & 7;
    for (int il = t; il < PREP_HALF; il += PREP_THREADS) {
        float s0 = W2[il + 0] - W1[il + 0];
        float s1 = W2[il + 1] - W1[il + 1];
        float s2 = W2[il + 2] - W1[il + 2];
        float s3 = W2[il + 3] - W1[il + 3];
        float A = s1;
        float B = 0.5f * (s2 - s0);
        float C = s0 - 2.5f * s1 + 2.0f * s2 - 0.5f * s3;
        float D = 0.5f * (s3 - s0) + 1.5f * (s1 - s2);
        g_coef[(g * NK + i0 + il) * GRP + cg] = make_float4(A, B, C, D);
    }
}

// Main: SMEM table, conflict-free LDS.128 gather, 32 warps/SM, single wave.
// grid = (NCHUNK, NGRP), 1024 threads.
__global__ void __launch_bounds__(MAIN_THREADS)
de_main(const float* __restrict__ xin, float* __restrict__ out, int rows) {
    extern __shared__ float4 s_tab[];      // [NK][GRP]
    const int t = threadIdx.x;
    const int g = blockIdx.y;

    const float4* __restrict__ gsrc = g_coef + g * NK * GRP;
#pragma unroll
    for (int j = 0; j < (NK * GRP) / MAIN_THREADS; j++)
        s_tab[j * MAIN_THREADS + t] = __ldg(&gsrc[j * MAIN_THREADS + t]);
    __syncthreads();

    const int c   = t & (GRP - 1);
    const int rl  = t >> 3;                // 0..127
    const int col = g * GRP + c;

    const int chunk  = blockIdx.x;
    const int rbase  = rows / NCHUNK;
    const int rextra = rows - rbase * NCHUNK;
    const int r0     = chunk * rbase + min(chunk, rextra);
    const int nrows  = rbase + (chunk < rextra ? 1 : 0);
    const int r_end  = r0 + nrows;

    int r = r0 + rl;
    const int nfull = nrows / (ROWS_PER_ITER * UB);

    for (int b = 0; b < nfull; b++) {
        float v[UB];
#pragma unroll
        for (int u = 0; u < UB; u++)
            v[u] = __ldcs(&xin[(r + u * ROWS_PER_ITER) * CHANNELS + col]);
#pragma unroll
        for (int u = 0; u < UB; u++) {
            float uu = fmaf(v[u], INV_H, V_OFF);
            uu = fminf(fmaxf(uu, 0.0f), (float)NK - 0.001f);
            int i = (int)uu;
            float tf = uu - (float)i;
            float4 C = s_tab[i * GRP + c];
            __stcs(&out[(r + u * ROWS_PER_ITER) * CHANNELS + col],
                   fmaf(tf, fmaf(tf, fmaf(tf, C.w, C.z), C.y), C.x));
        }
        r += ROWS_PER_ITER * UB;
    }

    // remainder: UB=4 batches
    while (r + 3 * ROWS_PER_ITER < r_end) {
        float v[4];
#pragma unroll
        for (int u = 0; u < 4; u++)
            v[u] = __ldcs(&xin[(r + u * ROWS_PER_ITER) * CHANNELS + col]);
#pragma unroll
        for (int u = 0; u < 4; u++) {
            float uu = fmaf(v[u], INV_H, V_OFF);
            uu = fminf(fmaxf(uu, 0.0f), (float)NK - 0.001f);
            int i = (int)uu;
            float tf = uu - (float)i;
            float4 C = s_tab[i * GRP + c];
            __stcs(&out[(r + u * ROWS_PER_ITER) * CHANNELS + col],
                   fmaf(tf, fmaf(tf, fmaf(tf, C.w, C.z), C.y), C.x));
        }
        r += 4 * ROWS_PER_ITER;
    }
    for (; r < r_end; r += ROWS_PER_ITER) {
        float v = __ldcs(&xin[r * CHANNELS + col]);
        float uu = fmaf(v, INV_H, V_OFF);
        uu = fminf(fmaxf(uu, 0.0f), (float)NK - 0.001f);
        int i = (int)uu;
        float tf = uu - (float)i;
        float4 C = s_tab[i * GRP + c];
        __stcs(&out[r * CHANNELS + col],
               fmaf(tf, fmaf(tf, fmaf(tf, C.w, C.z), C.y), C.x));
    }
}

// ---------------------------------------------------------------------------

extern "C" void kernel_launch(void* const* d_in, const int* in_sizes, int n_in,
                              void* d_out, int out_size) {
    const float* x  = (const float*)d_in[0];
    const float* a0 = (const float*)d_in[1];
    const float* a1 = (const float*)d_in[2];
    const float* a2 = (const float*)d_in[3];
    const float* b0 = (const float*)d_in[4];
    const float* b1 = (const float*)d_in[5];
    const float* b2 = (const float*)d_in[6];
    const float* b3 = (const float*)d_in[7];
    const float* H0 = (const float*)d_in[8];
    const float* H1 = (const float*)d_in[9];
    const float* H2 = (const float*)d_in[10];
    const float* H3 = (const float*)d_in[11];
    float* out = (float*)d_out;

    int total = in_sizes[0];
    int rows  = total / CHANNELS;    // 65536

    static int smem_set = 0;
    if (!smem_set) {
        cudaFuncSetAttribute(de_main, cudaFuncAttributeMaxDynamicSharedMemorySize,
                             SMEM_BYTES);
        smem_set = 1;
    }

    dim3 pgrid(CHANNELS, 2);
    de_prep<<<pgrid, PREP_THREADS>>>(a0, a1, a2, b0, b1, b2, b3, H0, H1, H2, H3);
    dim3 mgrid(NCHUNK, NGRP);
    de_main<<<mgrid, MAIN_THREADS, SMEM_BYTES>>>(x, out, rows);
}

// round 7
// speedup vs baseline: 1.3607x; 1.0962x over previous
#include <cuda_runtime.h>
#include <math.h>

#define CHANNELS 192
#define CPARAMS  43

// Table: v range [-6.5, 6.5], step h = 1/64
#define NK      832              // 13 * 64 intervals per channel
#define OFFK    64               // 1.0 / h
#define NC      (NK + OFFK + 3)  // 899 CDF samples per channel
#define H_STEP  (1.0f / 64.0f)
#define INV_H   64.0f
#define V_OFF   416.0f           // 6.5 * 64

#define GRP      8                       // channels per main-kernel block
#define NGRP     (CHANNELS / GRP)        // 24
#define NCHUNK   12                      // 24*12 = 288 blocks ~ one wave @ 2 CTA/SM
#define MAIN_THREADS 1024
#define ROWS_PER_ITER (MAIN_THREADS / GRP)   // 128
#define UB 8
#define SMEM_BYTES (NK * GRP * 16)       // 106,496 B -> 2 CTAs/SM

// Cubic coefficients, transposed per group: g_coef[(g*NK + i)*GRP + c] (~2.6 MB)
__device__ float4 g_coef[NGRP * NK * GRP];

// ---------------------------------------------------------------------------

__device__ __forceinline__ float softplus_acc(float v) {
    return fmaxf(v, 0.0f) + log1pf(expf(-fabsf(v)));
}
__device__ __forceinline__ float tanh_fast(float x) {
    x = fminf(fmaxf(x, -20.0f), 20.0f);
    float e = __expf(-2.0f * x);
    return __fdividef(1.0f - e, 1.0f + e);
}
__device__ __forceinline__ float sigmoid_fast(float x) {
    return __fdividef(1.0f, 1.0f + __expf(-x));
}

__device__ __forceinline__ float cdf_eval(float u, const float* __restrict__ K) {
    float h[3];
#pragma unroll
    for (int j = 0; j < 3; j++) {
        h[j] = fmaf(u, K[j], K[3 + j]);
        h[j] = fmaf(K[6 + j], tanh_fast(h[j]), h[j]);
    }
    float y[3];
#pragma unroll
    for (int p = 0; p < 3; p++) y[p] = K[18 + p];
#pragma unroll
    for (int i = 0; i < 3; i++)
#pragma unroll
        for (int p = 0; p < 3; p++) y[p] = fmaf(h[i], K[9 + i * 3 + p], y[p]);
#pragma unroll
    for (int j = 0; j < 3; j++) y[j] = fmaf(K[21 + j], tanh_fast(y[j]), y[j]);
    float z[3];
#pragma unroll
    for (int p = 0; p < 3; p++) z[p] = K[33 + p];
#pragma unroll
    for (int i = 0; i < 3; i++)
#pragma unroll
        for (int p = 0; p < 3; p++) z[p] = fmaf(y[i], K[24 + i * 3 + p], z[p]);
#pragma unroll
    for (int j = 0; j < 3; j++) z[j] = fmaf(K[36 + j], tanh_fast(z[j]), z[j]);
    float f = K[42];
#pragma unroll
    for (int i = 0; i < 3; i++) f = fmaf(z[i], K[39 + i], f);
    return sigmoid_fast(f);
}

// Fused prep: one block per channel. Sample all NC=899 CDF values into SMEM,
// then emit Catmull-Rom coefficients. grid = CHANNELS, 256 threads.
#define PREP_THREADS 256
__global__ void __launch_bounds__(PREP_THREADS)
de_prep(const float* __restrict__ a0, const float* __restrict__ a1,
        const float* __restrict__ a2,
        const float* __restrict__ b0, const float* __restrict__ b1,
        const float* __restrict__ b2, const float* __restrict__ b3,
        const float* __restrict__ H0, const float* __restrict__ H1,
        const float* __restrict__ H2, const float* __restrict__ H3) {
    __shared__ float sk[CPARAMS];
    __shared__ float W[NC];
    const int c = blockIdx.x;
    const int t = threadIdx.x;

    if (t < CPARAMS) {
        float v;
        if      (t < 3)  v = softplus_acc(H0[c * 3 + t]);
        else if (t < 6)  v = b0[c * 3 + (t - 3)];
        else if (t < 9)  v = tanhf(a0[c * 3 + (t - 6)]);
        else if (t < 18) v = softplus_acc(H1[c * 9 + (t - 9)]);
        else if (t < 21) v = b1[c * 3 + (t - 18)];
        else if (t < 24) v = tanhf(a1[c * 3 + (t - 21)]);
        else if (t < 33) v = softplus_acc(H2[c * 9 + (t - 24)]);
        else if (t < 36) v = b2[c * 3 + (t - 33)];
        else if (t < 39) v = tanhf(a2[c * 3 + (t - 36)]);
        else if (t < 42) v = softplus_acc(H3[c * 3 + (t - 39)]);
        else             v = b3[c];
        sk[t] = v;
    }
    __syncthreads();

    const float u0 = -7.0f - H_STEP;     // cs[j] = cdf(u0 + j*h)
#pragma unroll
    for (int j = t; j < NC; j += PREP_THREADS) {
        float u = fmaf((float)j, H_STEP, u0);
        W[j] = cdf_eval(u, sk);
    }
    __syncthreads();

    const int g  = c >> 3;
    const int cg = c & 7;
    for (int i = t; i < NK; i += PREP_THREADS) {
        float s0 = W[i + 0 + OFFK] - W[i + 0];
        float s1 = W[i + 1 + OFFK] - W[i + 1];
        float s2 = W[i + 2 + OFFK] - W[i + 2];
        float s3 = W[i + 3 + OFFK] - W[i + 3];
        float A = s1;
        float B = 0.5f * (s2 - s0);
        float C = s0 - 2.5f * s1 + 2.0f * s2 - 0.5f * s3;
        float D = 0.5f * (s3 - s0) + 1.5f * (s1 - s2);
        g_coef[(g * NK + i) * GRP + cg] = make_float4(A, B, C, D);
    }
}

// Main: SMEM table (106.5 KB -> 2 CTAs/SM, occ 100%), conflict-free LDS.128.
// grid = (NCHUNK, NGRP), 1024 threads, forced <=32 regs.
__global__ void __launch_bounds__(MAIN_THREADS, 2)
de_main(const float* __restrict__ xin, float* __restrict__ out, int rows) {
    extern __shared__ float4 s_tab[];      // [NK][GRP]
    const int t = threadIdx.x;
    const int g = blockIdx.y;

    const float4* __restrict__ gsrc = g_coef + g * NK * GRP;
    for (int j = t; j < NK * GRP; j += MAIN_THREADS)
        s_tab[j] = __ldg(&gsrc[j]);
    __syncthreads();

    const int c   = t & (GRP - 1);
    const int rl  = t >> 3;                // 0..127
    const int col = g * GRP + c;

    const int chunk  = blockIdx.x;
    const int rbase  = rows / NCHUNK;
    const int rextra = rows - rbase * NCHUNK;
    const int r0     = chunk * rbase + min(chunk, rextra);
    const int nrows  = rbase + (chunk < rextra ? 1 : 0);
    const int r_end  = r0 + nrows;

    int r = r0 + rl;
    const int nfull = nrows / (ROWS_PER_ITER * UB);

    for (int b = 0; b < nfull; b++) {
        float v[UB];
#pragma unroll
        for (int u = 0; u < UB; u++)
            v[u] = __ldcs(&xin[(r + u * ROWS_PER_ITER) * CHANNELS + col]);
#pragma unroll
        for (int u = 0; u < UB; u++) {
            float uu = fmaf(v[u], INV_H, V_OFF);
            uu = fminf(fmaxf(uu, 0.0f), (float)NK - 0.001f);
            int i = (int)uu;
            float tf = uu - (float)i;
            float4 C = s_tab[i * GRP + c];
            __stcs(&out[(r + u * ROWS_PER_ITER) * CHANNELS + col],
                   fmaf(tf, fmaf(tf, fmaf(tf, C.w, C.z), C.y), C.x));
        }
        r += ROWS_PER_ITER * UB;
    }

    // remainder: UB=4 batches then scalar
    while (r + 3 * ROWS_PER_ITER < r_end) {
        float v[4];
#pragma unroll
        for (int u = 0; u < 4; u++)
            v[u] = __ldcs(&xin[(r + u * ROWS_PER_ITER) * CHANNELS + col]);
#pragma unroll
        for (int u = 0; u < 4; u++) {
            float uu = fmaf(v[u], INV_H, V_OFF);
            uu = fminf(fmaxf(uu, 0.0f), (float)NK - 0.001f);
            int i = (int)uu;
            float tf = uu - (float)i;
            float4 C = s_tab[i * GRP + c];
            __stcs(&out[(r + u * ROWS_PER_ITER) * CHANNELS + col],
                   fmaf(tf, fmaf(tf, fmaf(tf, C.w, C.z), C.y), C.x));
        }
        r += 4 * ROWS_PER_ITER;
    }
    for (; r < r_end; r += ROWS_PER_ITER) {
        float v = __ldcs(&xin[r * CHANNELS + col]);
        float uu = fmaf(v, INV_H, V_OFF);
        uu = fminf(fmaxf(uu, 0.0f), (float)NK - 0.001f);
        int i = (int)uu;
        float tf = uu - (float)i;
        float4 C = s_tab[i * GRP + c];
        __stcs(&out[r * CHANNELS + col],
               fmaf(tf, fmaf(tf, fmaf(tf, C.w, C.z), C.y), C.x));
    }
}

// ---------------------------------------------------------------------------

extern "C" void kernel_launch(void* const* d_in, const int* in_sizes, int n_in,
                              void* d_out, int out_size) {
    const float* x  = (const float*)d_in[0];
    const float* a0 = (const float*)d_in[1];
    const float* a1 = (const float*)d_in[2];
    const float* a2 = (const float*)d_in[3];
    const float* b0 = (const float*)d_in[4];
    const float* b1 = (const float*)d_in[5];
    const float* b2 = (const float*)d_in[6];
    const float* b3 = (const float*)d_in[7];
    const float* H0 = (const float*)d_in[8];
    const float* H1 = (const float*)d_in[9];
    const float* H2 = (const float*)d_in[10];
    const float* H3 = (const float*)d_in[11];
    float* out = (float*)d_out;

    int total = in_sizes[0];
    int rows  = total / CHANNELS;    // 65536

    static int smem_set = 0;
    if (!smem_set) {
        cudaFuncSetAttribute(de_main, cudaFuncAttributeMaxDynamicSharedMemorySize,
                             SMEM_BYTES);
        smem_set = 1;
    }

    de_prep<<<CHANNELS, PREP_THREADS>>>(a0, a1, a2, b0, b1, b2, b3,
                                        H0, H1, H2, H3);
    dim3 mgrid(NCHUNK, NGRP);
    de_main<<<mgrid, MAIN_THREADS, SMEM_BYTES>>>(x, out, rows);
}